// round 5
// baseline (speedup 1.0000x reference)
#include <cuda_runtime.h>

// Problem constants
#define BB 16
#define DD 256
#define TT 2048
#define KK 8192
#define NN (BB*TT)          // 32768 tokens
#define QN (BB*DD*TT)       // 8388608 quantized elements

// GEMM/argmin tiling
#define MT 128              // tokens per block
#define NT 128              // codes per tile
#define KC 16               // D-chunk
#define EPAD 132            // padded smem stride for emb tile (16B-aligned rows)

#define P2_BLOCKS (QN/1024) // 8192 gather/loss blocks

// Scratch (no allocations allowed -> device globals)
__device__ float g_norms[KK];
__device__ float g_zn2[NN];
__device__ int   g_idx[NN];
__device__ float g_partials[P2_BLOCKS];

// ---------------- kernel 0: codebook row norms (fp32, sequential-d FMA) ----------
__global__ void norms_kernel(const float* __restrict__ emb) {
    int k = blockIdx.x * blockDim.x + threadIdx.x;
    if (k >= KK) return;
    const float4* row = (const float4*)(emb + (size_t)k * DD);
    float s = 0.f;
#pragma unroll
    for (int i = 0; i < DD/4; i++) {
        float4 v = row[i];
        s = fmaf(v.x, v.x, s);
        s = fmaf(v.y, v.y, s);
        s = fmaf(v.z, v.z, s);
        s = fmaf(v.w, v.w, s);
    }
    g_norms[k] = s;
}

// ---------------- kernel 0b: per-token ||z||^2 ------------------------------------
__global__ void zn2_kernel(const float* __restrict__ z) {
    int n = blockIdx.x * blockDim.x + threadIdx.x;
    if (n >= NN) return;
    int b = n / TT, t = n % TT;
    const float* base = z + (size_t)b * DD * TT + t;
    float s = 0.f;
#pragma unroll 8
    for (int d = 0; d < DD; d++) {
        float v = base[(size_t)d * TT];
        s = fmaf(v, v, s);
    }
    g_zn2[n] = s;
}

// ---------------- kernel 1: fused distance GEMM + argmin --------------------------
// Block: 256 threads = 16x16 grid of (ty, tx); each thread owns 8 tokens x 8 codes.
// Tile: MT=128 tokens x NT=128 codes, D accumulated in KC=16 smem chunks.
__global__ __launch_bounds__(256) void
argmin_kernel(const float* __restrict__ z, const float* __restrict__ emb) {
    __shared__ __align__(16) float zs[KC][MT];
    __shared__ __align__(16) float es[KC][EPAD];
    __shared__ float rv[MT][16];
    __shared__ int   ri[MT][16];

    int tid = threadIdx.x;
    int tx = tid & 15, ty = tid >> 4;
    int token0 = blockIdx.x * MT;               // tile never straddles a batch (2048 % 128 == 0)
    int b = token0 / TT, t0 = token0 % TT;
    const float* zbase = z + (size_t)b * DD * TT + t0;

    float zn2v[8];
#pragma unroll
    for (int i = 0; i < 8; i++) zn2v[i] = g_zn2[token0 + ty*8 + i];

    float minv[8]; int mini[8];
#pragma unroll
    for (int i = 0; i < 8; i++) { minv[i] = 3.4028235e38f; mini[i] = 0; }

    for (int k0 = 0; k0 < KK; k0 += NT) {
        float acc[8][8];
#pragma unroll
        for (int i = 0; i < 8; i++)
#pragma unroll
            for (int j = 0; j < 8; j++) acc[i][j] = 0.f;

        for (int d0 = 0; d0 < DD; d0 += KC) {
            __syncthreads();
            // z chunk: [KC][MT], rows are contiguous-token slabs (coalesced float4)
            {
                int r = tid >> 5;        // 0..7
                int c = tid & 31;        // float4 column
#pragma unroll
                for (int h = 0; h < 2; h++) {
                    int rr = r + h*8;
                    float4 v = *(const float4*)(zbase + (size_t)(d0 + rr) * TT + c*4);
                    *(float4*)&zs[rr][c*4] = v;
                }
            }
            // emb chunk: transpose [code][d] -> es[d][code]
#pragma unroll
            for (int h = 0; h < 2; h++) {
                int f = tid + h*256;     // 0..511
                int code = f >> 2, d4 = (f & 3) * 4;
                float4 v = *(const float4*)(emb + (size_t)(k0 + code) * DD + d0 + d4);
                es[d4+0][code] = v.x;
                es[d4+1][code] = v.y;
                es[d4+2][code] = v.z;
                es[d4+3][code] = v.w;
            }
            __syncthreads();
#pragma unroll
            for (int d = 0; d < KC; d++) {
                float za[8], ea[8];
                *(float4*)&za[0] = *(const float4*)&zs[d][ty*8];
                *(float4*)&za[4] = *(const float4*)&zs[d][ty*8 + 4];
                *(float4*)&ea[0] = *(const float4*)&es[d][tx*8];
                *(float4*)&ea[4] = *(const float4*)&es[d][tx*8 + 4];
#pragma unroll
                for (int i = 0; i < 8; i++)
#pragma unroll
                    for (int j = 0; j < 8; j++)
                        acc[i][j] = fmaf(za[i], ea[j], acc[i][j]);
            }
        }

        // distances = fl( fl(zn2 + ek2) - 2*dot ), running argmin (lowest idx on ties)
        float cn[8];
#pragma unroll
        for (int j = 0; j < 8; j++) cn[j] = g_norms[k0 + tx*8 + j];
#pragma unroll
        for (int i = 0; i < 8; i++) {
#pragma unroll
            for (int j = 0; j < 8; j++) {
                float s = zn2v[i] + cn[j];
                float dist = s - 2.f * acc[i][j];   // 2*acc exact; single rounding on sub
                int idx = k0 + tx*8 + j;
                if (dist < minv[i] || (dist == minv[i] && idx < mini[i])) {
                    minv[i] = dist; mini[i] = idx;
                }
            }
        }
    }

    // cross-thread (tx) reduction per token
    __syncthreads();
#pragma unroll
    for (int i = 0; i < 8; i++) { rv[ty*8 + i][tx] = minv[i]; ri[ty*8 + i][tx] = mini[i]; }
    __syncthreads();
    if (tid < MT) {
        float bv = rv[tid][0]; int bi = ri[tid][0];
#pragma unroll
        for (int x = 1; x < 16; x++) {
            float v = rv[tid][x]; int id = ri[tid][x];
            if (v < bv || (v == bv && id < bi)) { bv = v; bi = id; }
        }
        g_idx[token0 + tid] = bi;
    }
}

// ---------------- kernel 2: gather quantized + partial loss -----------------------
// Each thread handles 4 consecutive t for one (b,d): coalesced z read + out write.
__global__ __launch_bounds__(256) void
gather_loss_kernel(const float* __restrict__ z, const float* __restrict__ emb,
                   float* __restrict__ out) {
    __shared__ float red[256];
    int unit = blockIdx.x * 256 + threadIdx.x;
    int e0 = unit * 4;                  // flat index into [B,D,T]
    int t  = e0 % TT;
    int bd = e0 / TT;
    int d  = bd % DD;
    int b  = bd / DD;
    int nb = b * TT + t;

    float4 zv = *(const float4*)(z + e0);
    int i0 = g_idx[nb + 0], i1 = g_idx[nb + 1], i2 = g_idx[nb + 2], i3 = g_idx[nb + 3];
    float4 qv;
    qv.x = emb[(size_t)i0 * DD + d];
    qv.y = emb[(size_t)i1 * DD + d];
    qv.z = emb[(size_t)i2 * DD + d];
    qv.w = emb[(size_t)i3 * DD + d];
    *(float4*)(out + e0) = qv;          // quantized_st == quantized numerically

    float dx = qv.x - zv.x, dy = qv.y - zv.y, dz = qv.z - zv.z, dw = qv.w - zv.w;
    red[threadIdx.x] = dx*dx + dy*dy + dz*dz + dw*dw;
    __syncthreads();
#pragma unroll
    for (int o = 128; o > 0; o >>= 1) {
        if (threadIdx.x < o) red[threadIdx.x] += red[threadIdx.x + o];
        __syncthreads();
    }
    if (threadIdx.x == 0) g_partials[blockIdx.x] = red[0];  // deterministic (no atomics)
}

// ---------------- kernel 3: finalize loss (fixed-order double reduce) -------------
__global__ void finalize_kernel(float* __restrict__ out, int out_size) {
    __shared__ double red[256];
    double s = 0.0;
    for (int i = threadIdx.x; i < P2_BLOCKS; i += 256) s += (double)g_partials[i];
    red[threadIdx.x] = s;
    __syncthreads();
#pragma unroll
    for (int o = 128; o > 0; o >>= 1) {
        if (threadIdx.x < o) red[threadIdx.x] += red[threadIdx.x + o];
        __syncthreads();
    }
    if (threadIdx.x == 0 && out_size > QN) {
        // loss = q_latent + 0.25*e_latent; both equal mean((q-z)^2) numerically
        out[QN] = (float)(1.25 * red[0] / (double)QN);
    }
}

// ---------------- kernel 4: indices as output dtype -------------------------------
__global__ void idxout_kernel(float* __restrict__ out) {
    int n = blockIdx.x * 256 + threadIdx.x;
    if (n < NN) out[QN + 1 + n] = (float)g_idx[n];
}

extern "C" void kernel_launch(void* const* d_in, const int* in_sizes, int n_in,
                              void* d_out, int out_size) {
    const float* z   = (const float*)d_in[0];
    const float* emb = (const float*)d_in[1];
    float* out = (float*)d_out;

    norms_kernel<<<KK/256, 256>>>(emb);
    zn2_kernel<<<NN/256, 256>>>(z);
    argmin_kernel<<<NN/MT, 256>>>(z, emb);
    gather_loss_kernel<<<QN/1024, 256>>>(z, emb, out);
    finalize_kernel<<<1, 256>>>(out, out_size);
    if (out_size >= QN + 1 + NN)
        idxout_kernel<<<(NN + 255)/256, 256>>>(out);
}

// round 6
// speedup vs baseline: 1.0024x; 1.0024x over previous
#include <cuda_runtime.h>

// Problem constants
#define BB 16
#define DD 256
#define TT 2048
#define KK 8192
#define NN (BB*TT)          // 32768 tokens
#define QN (BB*DD*TT)       // 8388608 quantized elements

// GEMM/argmin tiling
#define MT 128              // tokens per block
#define NT 128              // codes per tile
#define KC 16               // D-chunk
#define EPAD 132            // padded smem stride for emb tile (16B-aligned rows)

#define P2_BLOCKS (QN/1024) // 8192 gather/loss blocks

// Scratch (no allocations allowed -> device globals)
__device__ float g_norms[KK];
__device__ float g_zn2[NN];
__device__ int   g_idx[NN];
__device__ float g_partials[P2_BLOCKS];

// ---------------- kernel 0: codebook row norms (fp32, sequential-d FMA) ----------
__global__ void norms_kernel(const float* __restrict__ emb) {
    int k = blockIdx.x * blockDim.x + threadIdx.x;
    if (k >= KK) return;
    const float4* row = (const float4*)(emb + (size_t)k * DD);
    float s = 0.f;
#pragma unroll
    for (int i = 0; i < DD/4; i++) {
        float4 v = row[i];
        s = fmaf(v.x, v.x, s);
        s = fmaf(v.y, v.y, s);
        s = fmaf(v.z, v.z, s);
        s = fmaf(v.w, v.w, s);
    }
    g_norms[k] = s;
}

// ---------------- kernel 0b: per-token ||z||^2 ------------------------------------
__global__ void zn2_kernel(const float* __restrict__ z) {
    int n = blockIdx.x * blockDim.x + threadIdx.x;
    if (n >= NN) return;
    int b = n / TT, t = n % TT;
    const float* base = z + (size_t)b * DD * TT + t;
    float s = 0.f;
#pragma unroll 8
    for (int d = 0; d < DD; d++) {
        float v = base[(size_t)d * TT];
        s = fmaf(v, v, s);
    }
    g_zn2[n] = s;
}

// ---------------- kernel 1: fused distance GEMM + argmin --------------------------
// Block: 256 threads = 16x16 grid of (ty, tx); each thread owns 8 tokens x 8 codes.
// Tile: MT=128 tokens x NT=128 codes, D accumulated in KC=16 smem chunks.
__global__ __launch_bounds__(256) void
argmin_kernel(const float* __restrict__ z, const float* __restrict__ emb) {
    __shared__ __align__(16) float zs[KC][MT];
    __shared__ __align__(16) float es[KC][EPAD];
    __shared__ float rv[MT][16];
    __shared__ int   ri[MT][16];

    int tid = threadIdx.x;
    int tx = tid & 15, ty = tid >> 4;
    int token0 = blockIdx.x * MT;               // tile never straddles a batch (2048 % 128 == 0)
    int b = token0 / TT, t0 = token0 % TT;
    const float* zbase = z + (size_t)b * DD * TT + t0;

    float zn2v[8];
#pragma unroll
    for (int i = 0; i < 8; i++) zn2v[i] = g_zn2[token0 + ty*8 + i];

    float minv[8]; int mini[8];
#pragma unroll
    for (int i = 0; i < 8; i++) { minv[i] = 3.4028235e38f; mini[i] = 0; }

    for (int k0 = 0; k0 < KK; k0 += NT) {
        float acc[8][8];
#pragma unroll
        for (int i = 0; i < 8; i++)
#pragma unroll
            for (int j = 0; j < 8; j++) acc[i][j] = 0.f;

        for (int d0 = 0; d0 < DD; d0 += KC) {
            __syncthreads();
            // z chunk: [KC][MT], rows are contiguous-token slabs (coalesced float4)
            {
                int r = tid >> 5;        // 0..7
                int c = tid & 31;        // float4 column
#pragma unroll
                for (int h = 0; h < 2; h++) {
                    int rr = r + h*8;
                    float4 v = *(const float4*)(zbase + (size_t)(d0 + rr) * TT + c*4);
                    *(float4*)&zs[rr][c*4] = v;
                }
            }
            // emb chunk: transpose [code][d] -> es[d][code]
#pragma unroll
            for (int h = 0; h < 2; h++) {
                int f = tid + h*256;     // 0..511
                int code = f >> 2, d4 = (f & 3) * 4;
                float4 v = *(const float4*)(emb + (size_t)(k0 + code) * DD + d0 + d4);
                es[d4+0][code] = v.x;
                es[d4+1][code] = v.y;
                es[d4+2][code] = v.z;
                es[d4+3][code] = v.w;
            }
            __syncthreads();
#pragma unroll
            for (int d = 0; d < KC; d++) {
                float za[8], ea[8];
                *(float4*)&za[0] = *(const float4*)&zs[d][ty*8];
                *(float4*)&za[4] = *(const float4*)&zs[d][ty*8 + 4];
                *(float4*)&ea[0] = *(const float4*)&es[d][tx*8];
                *(float4*)&ea[4] = *(const float4*)&es[d][tx*8 + 4];
#pragma unroll
                for (int i = 0; i < 8; i++)
#pragma unroll
                    for (int j = 0; j < 8; j++)
                        acc[i][j] = fmaf(za[i], ea[j], acc[i][j]);
            }
        }

        // distances = fl( fl(zn2 + ek2) - 2*dot ), running argmin (lowest idx on ties)
        float cn[8];
#pragma unroll
        for (int j = 0; j < 8; j++) cn[j] = g_norms[k0 + tx*8 + j];
#pragma unroll
        for (int i = 0; i < 8; i++) {
#pragma unroll
            for (int j = 0; j < 8; j++) {
                float s = zn2v[i] + cn[j];
                float dist = s - 2.f * acc[i][j];   // 2*acc exact; single rounding on sub
                int idx = k0 + tx*8 + j;
                if (dist < minv[i] || (dist == minv[i] && idx < mini[i])) {
                    minv[i] = dist; mini[i] = idx;
                }
            }
        }
    }

    // cross-thread (tx) reduction per token
    __syncthreads();
#pragma unroll
    for (int i = 0; i < 8; i++) { rv[ty*8 + i][tx] = minv[i]; ri[ty*8 + i][tx] = mini[i]; }
    __syncthreads();
    if (tid < MT) {
        float bv = rv[tid][0]; int bi = ri[tid][0];
#pragma unroll
        for (int x = 1; x < 16; x++) {
            float v = rv[tid][x]; int id = ri[tid][x];
            if (v < bv || (v == bv && id < bi)) { bv = v; bi = id; }
        }
        g_idx[token0 + tid] = bi;
    }
}

// ---------------- kernel 2: gather quantized + partial loss -----------------------
// Each thread handles 4 consecutive t for one (b,d): coalesced z read + out write.
__global__ __launch_bounds__(256) void
gather_loss_kernel(const float* __restrict__ z, const float* __restrict__ emb,
                   float* __restrict__ out) {
    __shared__ float red[256];
    int unit = blockIdx.x * 256 + threadIdx.x;
    int e0 = unit * 4;                  // flat index into [B,D,T]
    int t  = e0 % TT;
    int bd = e0 / TT;
    int d  = bd % DD;
    int b  = bd / DD;
    int nb = b * TT + t;

    float4 zv = *(const float4*)(z + e0);
    int i0 = g_idx[nb + 0], i1 = g_idx[nb + 1], i2 = g_idx[nb + 2], i3 = g_idx[nb + 3];
    float4 qv;
    qv.x = emb[(size_t)i0 * DD + d];
    qv.y = emb[(size_t)i1 * DD + d];
    qv.z = emb[(size_t)i2 * DD + d];
    qv.w = emb[(size_t)i3 * DD + d];
    *(float4*)(out + e0) = qv;          // quantized_st == quantized numerically

    float dx = qv.x - zv.x, dy = qv.y - zv.y, dz = qv.z - zv.z, dw = qv.w - zv.w;
    red[threadIdx.x] = dx*dx + dy*dy + dz*dz + dw*dw;
    __syncthreads();
#pragma unroll
    for (int o = 128; o > 0; o >>= 1) {
        if (threadIdx.x < o) red[threadIdx.x] += red[threadIdx.x + o];
        __syncthreads();
    }
    if (threadIdx.x == 0) g_partials[blockIdx.x] = red[0];  // deterministic (no atomics)
}

// ---------------- kernel 3: finalize loss (fixed-order double reduce) -------------
__global__ void finalize_kernel(float* __restrict__ out, int out_size) {
    __shared__ double red[256];
    double s = 0.0;
    for (int i = threadIdx.x; i < P2_BLOCKS; i += 256) s += (double)g_partials[i];
    red[threadIdx.x] = s;
    __syncthreads();
#pragma unroll
    for (int o = 128; o > 0; o >>= 1) {
        if (threadIdx.x < o) red[threadIdx.x] += red[threadIdx.x + o];
        __syncthreads();
    }
    if (threadIdx.x == 0 && out_size > QN) {
        // loss = q_latent + 0.25*e_latent; both equal mean((q-z)^2) numerically
        out[QN] = (float)(1.25 * red[0] / (double)QN);
    }
}

// ---------------- kernel 4: indices as output dtype -------------------------------
__global__ void idxout_kernel(float* __restrict__ out) {
    int n = blockIdx.x * 256 + threadIdx.x;
    if (n < NN) out[QN + 1 + n] = (float)g_idx[n];
}

extern "C" void kernel_launch(void* const* d_in, const int* in_sizes, int n_in,
                              void* d_out, int out_size) {
    const float* z   = (const float*)d_in[0];
    const float* emb = (const float*)d_in[1];
    float* out = (float*)d_out;

    norms_kernel<<<KK/256, 256>>>(emb);
    zn2_kernel<<<NN/256, 256>>>(z);
    argmin_kernel<<<NN/MT, 256>>>(z, emb);
    gather_loss_kernel<<<QN/1024, 256>>>(z, emb, out);
    finalize_kernel<<<1, 256>>>(out, out_size);
    if (out_size >= QN + 1 + NN)
        idxout_kernel<<<(NN + 255)/256, 256>>>(out);
}

// round 14
// speedup vs baseline: 3.5530x; 3.5444x over previous
#include <cuda_runtime.h>
#include <cuda_fp16.h>
#include <stdint.h>

// Problem constants
#define BB 16
#define DD 256
#define TT 2048
#define KK 8192
#define NN (BB*TT)          // 32768 tokens
#define QN (BB*DD*TT)       // 8388608 quantized elements
#define P2_BLOCKS (QN/1024)

// Single-term fp16 GEMM: dot' = sum z_fp16 * (8192*e)_fp16, fp32 accum
#define KP 256
#define KC 64               // K-chunk per stage
#define NCH (KP/KC)         // 4 chunks
#define MCTA 128            // tokens per CTA
#define NTILE 128           // codes per tile
#define NTILES (KK/NTILE)   // 64
#define TOTAL_IT (NTILES*NCH)   // 256

// SMEM: two stages, rows padded to 144B (conflict-free frag loads; validated R13)
#define ROWB 144
#define ASTG (128*ROWB)     // 18432
#define SM_A(s) ((s)*ASTG)
#define SM_B(s) (2*ASTG + (s)*ASTG)
#define SM_TOT (4*ASTG)     // 73728

#define MARGIN 1.5e-4f      // >= grid ulp(256) + 2*hard approx bound, with 2x slack

// Scratch (no allocations allowed -> device globals)
__device__ __align__(16) __half g_ah[(size_t)NN*KP];   // 16MB  z fp16 token-major
__device__ __align__(16) __half g_bh[(size_t)KK*KP];   // 4MB   8192*e fp16
__device__ __align__(16) float  g_zf[(size_t)NN*DD];   // 32MB  z fp32 token-major
__device__ float g_cval[(size_t)NN*64];                // 8MB   per-token candidates
__device__ int   g_cidx[(size_t)NN*64];                // 8MB
__device__ float g_norms[KK];
__device__ float g_zn2[NN];
__device__ int   g_idx[NN];
__device__ float g_partials[P2_BLOCKS];

// ---------------- mma.sync (baseline PTX, compiles at target sm_103) --------------
__device__ __forceinline__ void hmma(float& c0, float& c1, float& c2, float& c3,
    uint32_t a0, uint32_t a1, uint32_t a2, uint32_t a3, uint32_t b0, uint32_t b1) {
    asm volatile("mma.sync.aligned.m16n8k16.row.col.f32.f16.f16.f32 "
        "{%0,%1,%2,%3}, {%4,%5,%6,%7}, {%8,%9}, {%0,%1,%2,%3};"
        : "+f"(c0), "+f"(c1), "+f"(c2), "+f"(c3)
        : "r"(a0), "r"(a1), "r"(a2), "r"(a3), "r"(b0), "r"(b1));
}

// ---------------- kernel: codebook row norms (reference rounding chain) -----------
__global__ void norms_kernel(const float* __restrict__ emb) {
    int k = blockIdx.x * blockDim.x + threadIdx.x;
    if (k >= KK) return;
    const float4* row = (const float4*)(emb + (size_t)k * DD);
    float s = 0.f;
#pragma unroll
    for (int i = 0; i < DD/4; i++) {
        float4 v = row[i];
        s = fmaf(v.x, v.x, s); s = fmaf(v.y, v.y, s);
        s = fmaf(v.z, v.z, s); s = fmaf(v.w, v.w, s);
    }
    g_norms[k] = s;
}

// ---------------- kernel: per-token ||z||^2 ---------------------------------------
__global__ void zn2_kernel(const float* __restrict__ z) {
    int n = blockIdx.x * blockDim.x + threadIdx.x;
    if (n >= NN) return;
    int b = n / TT, t = n % TT;
    const float* base = z + (size_t)b * DD * TT + t;
    float s = 0.f;
#pragma unroll 8
    for (int d = 0; d < DD; d++) {
        float v = base[(size_t)d * TT];
        s = fmaf(v, v, s);
    }
    g_zn2[n] = s;
}

// ---------------- prep: z -> token-major fp32 + fp16 ------------------------------
__global__ __launch_bounds__(256) void prep_z_kernel(const float* __restrict__ z) {
    __shared__ float sm[32][257];
    int n0 = blockIdx.x * 32;
    int b = n0 / TT, t0 = n0 % TT;
    int tid = threadIdx.x;
#pragma unroll
    for (int i = 0; i < 32; i++) {
        int flat = i*256 + tid;
        int d = flat >> 5, tl = flat & 31;
        sm[tl][d] = z[(size_t)b*DD*TT + (size_t)d*TT + t0 + tl];
    }
    __syncthreads();
#pragma unroll
    for (int u = 0; u < 2; u++) {
        int unit = u*256 + tid;             // 512 = 32 tok x 16 chunks
        int tok = unit >> 4, ch = unit & 15;
        __align__(16) float fb[16];
        __align__(16) __half hb[16];
#pragma unroll
        for (int j = 0; j < 16; j++) {
            float v = sm[tok][ch*16 + j];
            fb[j] = v;
            hb[j] = __float2half_rn(v);
        }
        float4* fdst = (float4*)(g_zf + (size_t)(n0 + tok)*DD + ch*16);
#pragma unroll
        for (int q = 0; q < 4; q++) fdst[q] = *(float4*)&fb[q*4];
        float4* hdst = (float4*)(g_ah + (size_t)(n0 + tok)*KP + ch*16);
        hdst[0] = *(float4*)&hb[0];
        hdst[1] = *(float4*)&hb[8];
    }
}

// ---------------- prep: emb -> fp16 (scaled by 8192, exact pow2) ------------------
__global__ __launch_bounds__(256) void prep_e_kernel(const float* __restrict__ emb) {
    int unit = blockIdx.x * 256 + threadIdx.x;   // KK*16 units
    int k = unit >> 4, ch = unit & 15;
    const float* src = emb + (size_t)k*DD + ch*16;
    __align__(16) __half hb[16];
#pragma unroll
    for (int j = 0; j < 16; j++)
        hb[j] = __float2half_rn(src[j] * 8192.f);
    float4* dst = (float4*)(g_bh + (size_t)k*KP + ch*16);
    dst[0] = *(float4*)&hb[0];
    dst[1] = *(float4*)&hb[8];
}

// top-4 ascending insert (compile-time slot)
#define INS4(sl, dd, id) do{ \
    float _d = (dd); \
    if (_d < tv##sl[3]) { int _i = (id); \
        if (_d < tv##sl[2]) { tv##sl[3]=tv##sl[2]; ti##sl[3]=ti##sl[2]; \
            if (_d < tv##sl[1]) { tv##sl[2]=tv##sl[1]; ti##sl[2]=ti##sl[1]; \
                if (_d < tv##sl[0]) { tv##sl[1]=tv##sl[0]; ti##sl[1]=ti##sl[0]; \
                    tv##sl[0]=_d; ti##sl[0]=_i; } \
                else { tv##sl[1]=_d; ti##sl[1]=_i; } } \
            else { tv##sl[2]=_d; ti##sl[2]=_i; } } \
        else { tv##sl[3]=_d; ti##sl[3]=_i; } } \
}while(0)

// ---------------- main: fp16 mma.sync approx distances + per-thread top-4 ---------
// 512 threads = 16 warps (4x4), warp tile 32x32. Structure validated in R13.
__global__ __launch_bounds__(512, 1) void argmin_mma_kernel() {
    extern __shared__ char smem[];
    int tid = threadIdx.x;
    int warp = tid >> 5, lane = tid & 31;
    int wm = warp >> 2, wn = warp & 3;
    int g8 = lane >> 2, tig = lane & 3;
    int token0 = blockIdx.x * MCTA;

    const float BIG = 3.4028235e38f;
    float tv0[4], tv1[4], tv2[4], tv3[4];
    int   ti0[4], ti1[4], ti2[4], ti3[4];
#pragma unroll
    for (int j = 0; j < 4; j++) {
        tv0[j]=BIG; tv1[j]=BIG; tv2[j]=BIG; tv3[j]=BIG;
        ti0[j]=0;   ti1[j]=0;   ti2[j]=0;   ti3[j]=0;
    }

    float acc[2][4][4];
    const __half* Abase = g_ah + (size_t)token0 * KP;

    float4 pa[2], pb[2];
#pragma unroll
    for (int i = 0; i < 2; i++) {
        int unit = i*512 + tid; int row = unit >> 3, c = unit & 7;
        pa[i] = *(const float4*)(Abase + (size_t)row*KP + c*8);
        pb[i] = *(const float4*)(g_bh + (size_t)row*KP + c*8);
    }
#pragma unroll
    for (int i = 0; i < 2; i++) {
        int unit = i*512 + tid; int row = unit >> 3, c = unit & 7;
        *(float4*)(smem + SM_A(0) + row*ROWB + c*16) = pa[i];
        *(float4*)(smem + SM_B(0) + row*ROWB + c*16) = pb[i];
    }
    __syncthreads();

    for (int g = 0; g < TOTAL_IT; g++) {
        int nt = g / NCH, kc = g - nt*NCH;
        int s = g & 1;
        bool hasNext = (g + 1 < TOTAL_IT);
        if (hasNext) {
            int gn = g + 1, nt2 = gn / NCH, kc2 = gn - nt2*NCH;
            const __half* Ab = Abase + kc2*KC;
            const __half* Bb = g_bh + (size_t)(nt2*NTILE) * KP + kc2*KC;
#pragma unroll
            for (int i = 0; i < 2; i++) {
                int unit = i*512 + tid; int row = unit >> 3, c = unit & 7;
                pa[i] = *(const float4*)(Ab + (size_t)row*KP + c*8);
                pb[i] = *(const float4*)(Bb + (size_t)row*KP + c*8);
            }
        }
        if (kc == 0) {
#pragma unroll
            for (int mi = 0; mi < 2; mi++)
#pragma unroll
            for (int ni = 0; ni < 4; ni++)
#pragma unroll
            for (int q = 0; q < 4; q++) acc[mi][ni][q] = 0.f;
        }
        const char* As = smem + SM_A(s);
        const char* Bs = smem + SM_B(s);
#pragma unroll
        for (int ks = 0; ks < 4; ks++) {
            uint32_t af[2][4], bf[4][2];
#pragma unroll
            for (int mi = 0; mi < 2; mi++) {
                int r0 = wm*32 + mi*16 + g8;
                const char* p = As + ks*32 + tig*4;
                af[mi][0] = *(const uint32_t*)(p + r0*ROWB);
                af[mi][1] = *(const uint32_t*)(p + (r0+8)*ROWB);
                af[mi][2] = *(const uint32_t*)(p + r0*ROWB + 16);
                af[mi][3] = *(const uint32_t*)(p + (r0+8)*ROWB + 16);
            }
#pragma unroll
            for (int ni = 0; ni < 4; ni++) {
                int r0 = wn*32 + ni*8 + g8;
                const char* p = Bs + ks*32 + tig*4 + r0*ROWB;
                bf[ni][0] = *(const uint32_t*)(p);
                bf[ni][1] = *(const uint32_t*)(p + 16);
            }
#pragma unroll
            for (int mi = 0; mi < 2; mi++)
#pragma unroll
            for (int ni = 0; ni < 4; ni++)
                hmma(acc[mi][ni][0], acc[mi][ni][1], acc[mi][ni][2], acc[mi][ni][3],
                     af[mi][0], af[mi][1], af[mi][2], af[mi][3], bf[ni][0], bf[ni][1]);
        }
        // tile end: approx dist (zn2 dropped: constant per token) + top-4 insert
        if (kc == NCH-1) {
            int codebase = nt*NTILE + wn*32;
#pragma unroll
            for (int ni = 0; ni < 4; ni++) {
                int c0 = codebase + ni*8 + tig*2;
                float cn0 = g_norms[c0], cn1 = g_norms[c0+1];
                // slot0 = (mi0,h0), slot1 = (mi0,h1), slot2 = (mi1,h0), slot3 = (mi1,h1)
                float d;
                d = fmaf(-0x1p-12f, acc[0][ni][0], cn0); INS4(0, d, c0);
                d = fmaf(-0x1p-12f, acc[0][ni][1], cn1); INS4(0, d, c0+1);
                d = fmaf(-0x1p-12f, acc[0][ni][2], cn0); INS4(1, d, c0);
                d = fmaf(-0x1p-12f, acc[0][ni][3], cn1); INS4(1, d, c0+1);
                d = fmaf(-0x1p-12f, acc[1][ni][0], cn0); INS4(2, d, c0);
                d = fmaf(-0x1p-12f, acc[1][ni][1], cn1); INS4(2, d, c0+1);
                d = fmaf(-0x1p-12f, acc[1][ni][2], cn0); INS4(3, d, c0);
                d = fmaf(-0x1p-12f, acc[1][ni][3], cn1); INS4(3, d, c0+1);
            }
        }
        if (hasNext) {
            int so = s ^ 1;
#pragma unroll
            for (int i = 0; i < 2; i++) {
                int unit = i*512 + tid; int row = unit >> 3, c = unit & 7;
                *(float4*)(smem + SM_A(so) + row*ROWB + c*16) = pa[i];
                *(float4*)(smem + SM_B(so) + row*ROWB + c*16) = pb[i];
            }
        }
        __syncthreads();
    }

    // write 4 candidates per (slot, thread): 64 per token total
    int part = wn*4 + tig;
#pragma unroll
    for (int sl = 0; sl < 4; sl++) {
        int r = wm*32 + (sl>>1)*16 + (sl&1)*8 + g8;
        size_t base = (size_t)(token0 + r)*64 + part*4;
        const float* tvp = (sl==0)?tv0:(sl==1)?tv1:(sl==2)?tv2:tv3;
        const int*   tip = (sl==0)?ti0:(sl==1)?ti1:(sl==2)?ti2:ti3;
#pragma unroll
        for (int j = 0; j < 4; j++) { g_cval[base+j] = tvp[j]; g_cidx[base+j] = tip[j]; }
    }
}

// ---------------- refinement: exact R1 chain on margin candidates -----------------
// One warp per token. Completeness: per-thread top-4 covers all codes within
// MARGIN of the approx min except P~5e-4 total.
__global__ __launch_bounds__(256) void refine_kernel(const float* __restrict__ emb) {
    int warp = threadIdx.x >> 5, lane = threadIdx.x & 31;
    int n = blockIdx.x * 8 + warp;
    size_t cb = (size_t)n * 64;
    float v0 = g_cval[cb + lane];
    float v1 = g_cval[cb + 32 + lane];
    float mv = fminf(v0, v1);
#pragma unroll
    for (int o = 16; o; o >>= 1) mv = fminf(mv, __shfl_xor_sync(0xFFFFFFFFu, mv, o));
    float thr = mv + MARGIN;
    float zn2 = g_zn2[n];
    const float* zr = g_zf + (size_t)n * DD;
    unsigned long long best = 0xFFFFFFFFFFFFFFFFull;
#pragma unroll 1
    for (int c = 0; c < 2; c++) {
        float v = c ? v1 : v0;
        if (v <= thr) {
            int idx = g_cidx[cb + c*32 + lane];
            const float* er = emb + (size_t)idx * DD;
            float dot = 0.f;
#pragma unroll 8
            for (int d = 0; d < DD; d++) dot = fmaf(zr[d], er[d], dot);
            float sdist = zn2 + g_norms[idx];
            float dist = sdist - 2.f * dot;          // exact R1 rounding chain
            unsigned long long p =
                ((unsigned long long)__float_as_uint(dist) << 32) | (unsigned)idx;
            if (p < best) best = p;
        }
    }
#pragma unroll
    for (int o = 16; o; o >>= 1) {
        unsigned long long ob = __shfl_xor_sync(0xFFFFFFFFu, best, o);
        if (ob < best) best = ob;
    }
    if (lane == 0) g_idx[n] = (int)(best & 0xFFFFFFFFull);
}

// ---------------- gather quantized + partial loss ---------------------------------
__global__ __launch_bounds__(256) void
gather_loss_kernel(const float* __restrict__ z, const float* __restrict__ emb,
                   float* __restrict__ out) {
    __shared__ float red[256];
    int unit = blockIdx.x * 256 + threadIdx.x;
    int e0 = unit * 4;
    int t  = e0 % TT;
    int bd = e0 / TT;
    int d  = bd % DD;
    int b  = bd / DD;
    int nb = b * TT + t;

    float4 zv = *(const float4*)(z + e0);
    int i0 = g_idx[nb + 0], i1 = g_idx[nb + 1], i2 = g_idx[nb + 2], i3 = g_idx[nb + 3];
    float4 qv;
    qv.x = emb[(size_t)i0 * DD + d];
    qv.y = emb[(size_t)i1 * DD + d];
    qv.z = emb[(size_t)i2 * DD + d];
    qv.w = emb[(size_t)i3 * DD + d];
    *(float4*)(out + e0) = qv;

    float dx = qv.x - zv.x, dy = qv.y - zv.y, dz = qv.z - zv.z, dw = qv.w - zv.w;
    red[threadIdx.x] = dx*dx + dy*dy + dz*dz + dw*dw;
    __syncthreads();
#pragma unroll
    for (int o = 128; o > 0; o >>= 1) {
        if (threadIdx.x < o) red[threadIdx.x] += red[threadIdx.x + o];
        __syncthreads();
    }
    if (threadIdx.x == 0) g_partials[blockIdx.x] = red[0];
}

// ---------------- finalize loss ----------------------------------------------------
__global__ void finalize_kernel(float* __restrict__ out, int out_size) {
    __shared__ double red[256];
    double s = 0.0;
    for (int i = threadIdx.x; i < P2_BLOCKS; i += 256) s += (double)g_partials[i];
    red[threadIdx.x] = s;
    __syncthreads();
#pragma unroll
    for (int o = 128; o > 0; o >>= 1) {
        if (threadIdx.x < o) red[threadIdx.x] += red[threadIdx.x + o];
        __syncthreads();
    }
    if (threadIdx.x == 0 && out_size > QN)
        out[QN] = (float)(1.25 * red[0] / (double)QN);
}

// ---------------- indices out ------------------------------------------------------
__global__ void idxout_kernel(float* __restrict__ out) {
    int n = blockIdx.x * 256 + threadIdx.x;
    if (n < NN) out[QN + 1 + n] = (float)g_idx[n];
}

extern "C" void kernel_launch(void* const* d_in, const int* in_sizes, int n_in,
                              void* d_out, int out_size) {
    const float* z   = (const float*)d_in[0];
    const float* emb = (const float*)d_in[1];
    float* out = (float*)d_out;

    cudaFuncSetAttribute(argmin_mma_kernel,
                         cudaFuncAttributeMaxDynamicSharedMemorySize, SM_TOT);

    prep_z_kernel<<<NN/32, 256>>>(z);
    prep_e_kernel<<<KK*16/256, 256>>>(emb);
    norms_kernel<<<KK/256, 256>>>(emb);
    zn2_kernel<<<NN/256, 256>>>(z);
    argmin_mma_kernel<<<NN/MCTA, 512, SM_TOT>>>();
    refine_kernel<<<NN/8, 256>>>(emb);
    gather_loss_kernel<<<QN/1024, 256>>>(z, emb, out);
    finalize_kernel<<<1, 256>>>(out, out_size);
    if (out_size >= QN + 1 + NN)
        idxout_kernel<<<(NN + 255)/256, 256>>>(out);
}

// round 15
// speedup vs baseline: 3.6799x; 1.0357x over previous
#include <cuda_runtime.h>
#include <cuda_fp16.h>
#include <stdint.h>

// Problem constants
#define BB 16
#define DD 256
#define TT 2048
#define KK 8192
#define NN (BB*TT)          // 32768 tokens
#define QN (BB*DD*TT)       // 8388608 quantized elements
#define P2_BLOCKS (QN/1024)

// Single-term fp16 GEMM: dot' = sum z_fp16 * (8192*e)_fp16, fp32 accum
#define KP 256
#define KC 64               // K-chunk per stage
#define NCH (KP/KC)         // 4 chunks
#define MCTA 128            // tokens per CTA
#define NTILE 128           // codes per tile
#define NTILES (KK/NTILE)   // 64
#define TOTAL_IT (NTILES*NCH)   // 256

// SMEM: 3 cp.async stages, rows padded to 144B (conflict-free ldmatrix phases)
#define ROWB 144
#define ASTG (128*ROWB)     // 18432
#define NSTG 3
#define SM_TOT (NSTG*2*ASTG)    // 110592

#define MARGIN 1.5e-4f      // >= grid ulp(256) + 2*hard approx bound, with 2x slack

// Scratch (no allocations allowed -> device globals)
__device__ __align__(16) __half g_ah[(size_t)NN*KP];   // 16MB  z fp16 token-major
__device__ __align__(16) __half g_bh[(size_t)KK*KP];   // 4MB   8192*e fp16
__device__ __align__(16) float  g_zf[(size_t)NN*DD];   // 32MB  z fp32 token-major
__device__ float g_cval[(size_t)NN*64];                // 8MB   per-token candidates
__device__ int   g_cidx[(size_t)NN*64];                // 8MB
__device__ float g_norms[KK];
__device__ float g_zn2[NN];
__device__ int   g_idx[NN];
__device__ float g_partials[P2_BLOCKS];

// ---------------- PTX helpers (all baseline features, compile at sm_103) ----------
__device__ __forceinline__ void hmma(float& c0, float& c1, float& c2, float& c3,
    uint32_t a0, uint32_t a1, uint32_t a2, uint32_t a3, uint32_t b0, uint32_t b1) {
    asm volatile("mma.sync.aligned.m16n8k16.row.col.f32.f16.f16.f32 "
        "{%0,%1,%2,%3}, {%4,%5,%6,%7}, {%8,%9}, {%0,%1,%2,%3};"
        : "+f"(c0), "+f"(c1), "+f"(c2), "+f"(c3)
        : "r"(a0), "r"(a1), "r"(a2), "r"(a3), "r"(b0), "r"(b1));
}
__device__ __forceinline__ void ldm_x4(uint32_t& r0, uint32_t& r1,
                                       uint32_t& r2, uint32_t& r3, uint32_t addr){
    asm volatile("ldmatrix.sync.aligned.m8n8.x4.shared.b16 {%0,%1,%2,%3}, [%4];"
        : "=r"(r0), "=r"(r1), "=r"(r2), "=r"(r3) : "r"(addr));
}
__device__ __forceinline__ void cpa16(uint32_t saddr, const void* g){
    asm volatile("cp.async.cg.shared.global [%0], [%1], 16;" :: "r"(saddr), "l"(g));
}
#define CP_COMMIT() asm volatile("cp.async.commit_group;" ::: "memory")
#define CP_WAIT(n)  asm volatile("cp.async.wait_group %0;" :: "n"(n) : "memory")

// ---------------- kernel: codebook row norms (reference rounding chain) -----------
__global__ void norms_kernel(const float* __restrict__ emb) {
    int k = blockIdx.x * blockDim.x + threadIdx.x;
    if (k >= KK) return;
    const float4* row = (const float4*)(emb + (size_t)k * DD);
    float s = 0.f;
#pragma unroll
    for (int i = 0; i < DD/4; i++) {
        float4 v = row[i];
        s = fmaf(v.x, v.x, s); s = fmaf(v.y, v.y, s);
        s = fmaf(v.z, v.z, s); s = fmaf(v.w, v.w, s);
    }
    g_norms[k] = s;
}

// ---------------- prep: z -> token-major fp32 + fp16, fused ||z||^2 ---------------
__global__ __launch_bounds__(256) void prep_z_kernel(const float* __restrict__ z) {
    __shared__ float sm[32][257];
    int n0 = blockIdx.x * 32;
    int b = n0 / TT, t0 = n0 % TT;
    int tid = threadIdx.x;
#pragma unroll
    for (int i = 0; i < 32; i++) {
        int flat = i*256 + tid;
        int d = flat >> 5, tl = flat & 31;
        sm[tl][d] = z[(size_t)b*DD*TT + (size_t)d*TT + t0 + tl];
    }
    __syncthreads();
    // fused zn2: same sequential-fmaf chain as reference (one thread per token)
    if (tid < 32) {
        float s = 0.f;
#pragma unroll 8
        for (int d = 0; d < DD; d++) { float v = sm[tid][d]; s = fmaf(v, v, s); }
        g_zn2[n0 + tid] = s;
    }
#pragma unroll
    for (int u = 0; u < 2; u++) {
        int unit = u*256 + tid;             // 512 = 32 tok x 16 chunks
        int tok = unit >> 4, ch = unit & 15;
        __align__(16) float fb[16];
        __align__(16) __half hb[16];
#pragma unroll
        for (int j = 0; j < 16; j++) {
            float v = sm[tok][ch*16 + j];
            fb[j] = v;
            hb[j] = __float2half_rn(v);
        }
        float4* fdst = (float4*)(g_zf + (size_t)(n0 + tok)*DD + ch*16);
#pragma unroll
        for (int q = 0; q < 4; q++) fdst[q] = *(float4*)&fb[q*4];
        float4* hdst = (float4*)(g_ah + (size_t)(n0 + tok)*KP + ch*16);
        hdst[0] = *(float4*)&hb[0];
        hdst[1] = *(float4*)&hb[8];
    }
}

// ---------------- prep: emb -> fp16 (scaled by 8192, exact pow2) ------------------
__global__ __launch_bounds__(256) void prep_e_kernel(const float* __restrict__ emb) {
    int unit = blockIdx.x * 256 + threadIdx.x;   // KK*16 units
    int k = unit >> 4, ch = unit & 15;
    const float* src = emb + (size_t)k*DD + ch*16;
    __align__(16) __half hb[16];
#pragma unroll
    for (int j = 0; j < 16; j++)
        hb[j] = __float2half_rn(src[j] * 8192.f);
    float4* dst = (float4*)(g_bh + (size_t)k*KP + ch*16);
    dst[0] = *(float4*)&hb[0];
    dst[1] = *(float4*)&hb[8];
}

// top-4 ascending insert (compile-time slot)
#define INS4(sl, dd, id) do{ \
    float _d = (dd); \
    if (_d < tv##sl[3]) { int _i = (id); \
        if (_d < tv##sl[2]) { tv##sl[3]=tv##sl[2]; ti##sl[3]=ti##sl[2]; \
            if (_d < tv##sl[1]) { tv##sl[2]=tv##sl[1]; ti##sl[2]=ti##sl[1]; \
                if (_d < tv##sl[0]) { tv##sl[1]=tv##sl[0]; ti##sl[1]=ti##sl[0]; \
                    tv##sl[0]=_d; ti##sl[0]=_i; } \
                else { tv##sl[1]=_d; ti##sl[1]=_i; } } \
            else { tv##sl[2]=_d; ti##sl[2]=_i; } } \
        else { tv##sl[3]=_d; ti##sl[3]=_i; } } \
}while(0)

// stage fill via cp.async: 4x 16B per thread (2 A + 2 B)
#define FILL(g_, st_) do{ \
    int _nt = (g_) / NCH, _kc = (g_) - _nt*NCH; \
    const __half* _Ab = Abase + _kc*KC; \
    const __half* _Bb = g_bh + (size_t)(_nt*NTILE)*KP + _kc*KC; \
    uint32_t _sA = smBase + (uint32_t)(st_)*(2*ASTG); \
    uint32_t _sB = _sA + ASTG; \
    _Pragma("unroll") \
    for (int _i = 0; _i < 2; _i++) { \
        int _unit = _i*512 + tid; int _row = _unit >> 3, _c = _unit & 7; \
        cpa16(_sA + _row*ROWB + _c*16, _Ab + (size_t)_row*KP + _c*8); \
        cpa16(_sB + _row*ROWB + _c*16, _Bb + (size_t)_row*KP + _c*8); \
    } \
}while(0)

// ---------------- main: fp16 mma.sync approx distances + per-thread top-4 ---------
// 512 threads = 16 warps (4x4), warp tile 32x32. ldmatrix frags + 3-stage cp.async.
__global__ __launch_bounds__(512, 1) void argmin_mma_kernel() {
    extern __shared__ char smem[];
    uint32_t smBase = (uint32_t)__cvta_generic_to_shared(smem);
    int tid = threadIdx.x;
    int warp = tid >> 5, lane = tid & 31;
    int wm = warp >> 2, wn = warp & 3;
    int g8 = lane >> 2, tig = lane & 3;
    int token0 = blockIdx.x * MCTA;

    // ldmatrix per-lane address components (loop-invariant)
    int a_row_in = (lane & 7) + ((lane >> 3) & 1) * 8;
    int a_col    = ((lane >> 4) & 1) * 16;
    int b_row_in = ((lane >> 4) & 1) * 8 + (lane & 7);
    int b_col    = ((lane >> 3) & 1) * 16;

    const float BIG = 3.4028235e38f;
    float tv0[4], tv1[4], tv2[4], tv3[4];
    int   ti0[4], ti1[4], ti2[4], ti3[4];
#pragma unroll
    for (int j = 0; j < 4; j++) {
        tv0[j]=BIG; tv1[j]=BIG; tv2[j]=BIG; tv3[j]=BIG;
        ti0[j]=0;   ti1[j]=0;   ti2[j]=0;   ti3[j]=0;
    }

    float acc[2][4][4];
    const __half* Abase = g_ah + (size_t)token0 * KP;

    // prologue: stages 0,1
    FILL(0, 0); CP_COMMIT();
    FILL(1, 1); CP_COMMIT();

    int stage = 0;
    for (int g = 0; g < TOTAL_IT; g++) {
        int nt = g >> 2, kc = g & (NCH-1);
        bool more = (g + 2 < TOTAL_IT);
        if (more) { CP_WAIT(1); } else { CP_WAIT(0); }
        __syncthreads();
        if (more) {
            int st2 = stage + 2; if (st2 >= NSTG) st2 -= NSTG;
            FILL(g + 2, st2); CP_COMMIT();
        }

        if (kc == 0) {
#pragma unroll
            for (int mi = 0; mi < 2; mi++)
#pragma unroll
            for (int ni = 0; ni < 4; ni++)
#pragma unroll
            for (int q = 0; q < 4; q++) acc[mi][ni][q] = 0.f;
        }
        uint32_t As = smBase + (uint32_t)stage*(2*ASTG);
        uint32_t Bs = As + ASTG;
#pragma unroll
        for (int ks = 0; ks < 4; ks++) {
            uint32_t af[2][4], bf[4][2];
#pragma unroll
            for (int mi = 0; mi < 2; mi++)
                ldm_x4(af[mi][0], af[mi][1], af[mi][2], af[mi][3],
                       As + (uint32_t)((wm*32 + mi*16 + a_row_in)*ROWB + ks*32 + a_col));
#pragma unroll
            for (int np = 0; np < 2; np++)
                ldm_x4(bf[np*2][0], bf[np*2][1], bf[np*2+1][0], bf[np*2+1][1],
                       Bs + (uint32_t)((wn*32 + np*16 + b_row_in)*ROWB + ks*32 + b_col));
#pragma unroll
            for (int mi = 0; mi < 2; mi++)
#pragma unroll
            for (int ni = 0; ni < 4; ni++)
                hmma(acc[mi][ni][0], acc[mi][ni][1], acc[mi][ni][2], acc[mi][ni][3],
                     af[mi][0], af[mi][1], af[mi][2], af[mi][3], bf[ni][0], bf[ni][1]);
        }
        // tile end: approx dist (zn2 constant per token, dropped) + top-4 insert
        if (kc == NCH-1) {
            int codebase = nt*NTILE + wn*32;
#pragma unroll
            for (int ni = 0; ni < 4; ni++) {
                int c0 = codebase + ni*8 + tig*2;
                float cn0 = g_norms[c0], cn1 = g_norms[c0+1];
                float d;
                d = fmaf(-0x1p-12f, acc[0][ni][0], cn0); INS4(0, d, c0);
                d = fmaf(-0x1p-12f, acc[0][ni][1], cn1); INS4(0, d, c0+1);
                d = fmaf(-0x1p-12f, acc[0][ni][2], cn0); INS4(1, d, c0);
                d = fmaf(-0x1p-12f, acc[0][ni][3], cn1); INS4(1, d, c0+1);
                d = fmaf(-0x1p-12f, acc[1][ni][0], cn0); INS4(2, d, c0);
                d = fmaf(-0x1p-12f, acc[1][ni][1], cn1); INS4(2, d, c0+1);
                d = fmaf(-0x1p-12f, acc[1][ni][2], cn0); INS4(3, d, c0);
                d = fmaf(-0x1p-12f, acc[1][ni][3], cn1); INS4(3, d, c0+1);
            }
        }
        stage++; if (stage >= NSTG) stage = 0;
    }

    // write 4 candidates per (slot, thread): 64 per token total
    int part = wn*4 + tig;
#pragma unroll
    for (int sl = 0; sl < 4; sl++) {
        int r = wm*32 + (sl>>1)*16 + (sl&1)*8 + g8;
        size_t base = (size_t)(token0 + r)*64 + part*4;
        const float* tvp = (sl==0)?tv0:(sl==1)?tv1:(sl==2)?tv2:tv3;
        const int*   tip = (sl==0)?ti0:(sl==1)?ti1:(sl==2)?ti2:ti3;
#pragma unroll
        for (int j = 0; j < 4; j++) { g_cval[base+j] = tvp[j]; g_cidx[base+j] = tip[j]; }
    }
}

// ---------------- refinement: exact R1 chain on margin candidates -----------------
__global__ __launch_bounds__(256) void refine_kernel(const float* __restrict__ emb) {
    int warp = threadIdx.x >> 5, lane = threadIdx.x & 31;
    int n = blockIdx.x * 8 + warp;
    size_t cb = (size_t)n * 64;
    float v0 = g_cval[cb + lane];
    float v1 = g_cval[cb + 32 + lane];
    float mv = fminf(v0, v1);
#pragma unroll
    for (int o = 16; o; o >>= 1) mv = fminf(mv, __shfl_xor_sync(0xFFFFFFFFu, mv, o));
    float thr = mv + MARGIN;
    float zn2 = g_zn2[n];
    const float* zr = g_zf + (size_t)n * DD;
    unsigned long long best = 0xFFFFFFFFFFFFFFFFull;
#pragma unroll 1
    for (int c = 0; c < 2; c++) {
        float v = c ? v1 : v0;
        if (v <= thr) {
            int idx = g_cidx[cb + c*32 + lane];
            const float* er = emb + (size_t)idx * DD;
            float dot = 0.f;
#pragma unroll 8
            for (int d = 0; d < DD; d++) dot = fmaf(zr[d], er[d], dot);
            float sdist = zn2 + g_norms[idx];
            float dist = sdist - 2.f * dot;          // exact R1 rounding chain
            unsigned long long p =
                ((unsigned long long)__float_as_uint(dist) << 32) | (unsigned)idx;
            if (p < best) best = p;
        }
    }
#pragma unroll
    for (int o = 16; o; o >>= 1) {
        unsigned long long ob = __shfl_xor_sync(0xFFFFFFFFu, best, o);
        if (ob < best) best = ob;
    }
    if (lane == 0) g_idx[n] = (int)(best & 0xFFFFFFFFull);
}

// ---------------- gather quantized + partial loss ---------------------------------
__global__ __launch_bounds__(256) void
gather_loss_kernel(const float* __restrict__ z, const float* __restrict__ emb,
                   float* __restrict__ out) {
    __shared__ float red[256];
    int unit = blockIdx.x * 256 + threadIdx.x;
    int e0 = unit * 4;
    int t  = e0 % TT;
    int bd = e0 / TT;
    int d  = bd % DD;
    int b  = bd / DD;
    int nb = b * TT + t;

    float4 zv = *(const float4*)(z + e0);
    int i0 = g_idx[nb + 0], i1 = g_idx[nb + 1], i2 = g_idx[nb + 2], i3 = g_idx[nb + 3];
    float4 qv;
    qv.x = emb[(size_t)i0 * DD + d];
    qv.y = emb[(size_t)i1 * DD + d];
    qv.z = emb[(size_t)i2 * DD + d];
    qv.w = emb[(size_t)i3 * DD + d];
    *(float4*)(out + e0) = qv;

    float dx = qv.x - zv.x, dy = qv.y - zv.y, dz = qv.z - zv.z, dw = qv.w - zv.w;
    red[threadIdx.x] = dx*dx + dy*dy + dz*dz + dw*dw;
    __syncthreads();
#pragma unroll
    for (int o = 128; o > 0; o >>= 1) {
        if (threadIdx.x < o) red[threadIdx.x] += red[threadIdx.x + o];
        __syncthreads();
    }
    if (threadIdx.x == 0) g_partials[blockIdx.x] = red[0];
}

// ---------------- finalize loss ----------------------------------------------------
__global__ void finalize_kernel(float* __restrict__ out, int out_size) {
    __shared__ double red[256];
    double s = 0.0;
    for (int i = threadIdx.x; i < P2_BLOCKS; i += 256) s += (double)g_partials[i];
    red[threadIdx.x] = s;
    __syncthreads();
#pragma unroll
    for (int o = 128; o > 0; o >>= 1) {
        if (threadIdx.x < o) red[threadIdx.x] += red[threadIdx.x + o];
        __syncthreads();
    }
    if (threadIdx.x == 0 && out_size > QN)
        out[QN] = (float)(1.25 * red[0] / (double)QN);
}

// ---------------- indices out ------------------------------------------------------
__global__ void idxout_kernel(float* __restrict__ out) {
    int n = blockIdx.x * 256 + threadIdx.x;
    if (n < NN) out[QN + 1 + n] = (float)g_idx[n];
}

extern "C" void kernel_launch(void* const* d_in, const int* in_sizes, int n_in,
                              void* d_out, int out_size) {
    const float* z   = (const float*)d_in[0];
    const float* emb = (const float*)d_in[1];
    float* out = (float*)d_out;

    cudaFuncSetAttribute(argmin_mma_kernel,
                         cudaFuncAttributeMaxDynamicSharedMemorySize, SM_TOT);

    prep_z_kernel<<<NN/32, 256>>>(z);
    prep_e_kernel<<<KK*16/256, 256>>>(emb);
    norms_kernel<<<KK/256, 256>>>(emb);
    argmin_mma_kernel<<<NN/MCTA, 512, SM_TOT>>>();
    refine_kernel<<<NN/8, 256>>>(emb);
    gather_loss_kernel<<<QN/1024, 256>>>(z, emb, out);
    finalize_kernel<<<1, 256>>>(out, out_size);
    if (out_size >= QN + 1 + NN)
        idxout_kernel<<<(NN + 255)/256, 256>>>(out);
}